// round 13
// baseline (speedup 1.0000x reference)
// R13: resubmission of the R11 kernel (R11+R12 both died on broker infra,
// "GB300 container failed twice", before execution — no kernel evidence).
#include <cuda_runtime.h>
#include <cuda_fp16.h>
#include <cstdint>

#define NN   50000
#define F    128
#define NCLS 40
#define MAXE 600000
#define SCB  512
#define NSB  ((NN + SCB - 1) / SCB)   // 98

// ---------------- scratch (__device__ globals; no allocations) -------------
__device__ float g_pt[NN * 256];       // layer1: t in cols 128..255 (stride 256); layer2: u in cols 40..79 (stride 80)
__device__ float g_h[NN * F];          // hidden activations
__device__ __half g_ph[NN * 128];      // half payload: p (layer1)
__device__ __half g_qh[NN * 40];       // half payload: q (layer2)
__device__ float g_wt1_hi[256 * F];    // [w1l|w1r]^T hi, k-permuted ([n][k])
__device__ float g_wt1_lo[256 * F];
__device__ float g_wt2_hi[80 * F];
__device__ float g_wt2_lo[80 * F];
__device__ int g_src[MAXE], g_dst[MAXE], g_csr[MAXE];
__device__ int g_cnt[NN], g_offs[NN], g_incl[NN];
__device__ int g_bsum[NSB], g_bexc[NSB];
__device__ int g_mode32;

// ---------------------------------------------------------------------------
__device__ __forceinline__ uint2 f2tf32p(float a) {
    uint2 r;
    asm("cvt.rna.tf32.f32 %0, %1;" : "=r"(r.x) : "f"(a));
    float t = a - __uint_as_float(r.x);
    asm("cvt.rna.tf32.f32 %0, %1;" : "=r"(r.y) : "f"(t));
    return r;
}

__global__ void detect_kernel(const void* ei) {
    if (threadIdx.x == 0 && blockIdx.x == 0) {
        const long long* p = (const long long*)ei;
        int m32 = 0;
        for (int i = 0; i < 16; i++) {
            long long v = p[i];
            if (v < 0 || v >= NN) { m32 = 1; break; }
        }
        g_mode32 = m32;
    }
}

__global__ void zero_int_kernel(int4* a, int n4) {
    int i = blockIdx.x * blockDim.x + threadIdx.x;
    int stride = gridDim.x * blockDim.x;
    int4 z = make_int4(0, 0, 0, 0);
    for (; i < n4; i += stride) a[i] = z;
}

// Build transposed, tf32-split weights, [n][k] with k permuted within each
// 8-block: pos = 2*(k%4) + (k/4)%2  (so frag pair (tig, tig+4) is adjacent).
__global__ void build_wcat_kernel(const float* __restrict__ w1l,
                                  const float* __restrict__ w1r,
                                  const float* __restrict__ w2l,
                                  const float* __restrict__ w2r,
                                  float* __restrict__ wt1_hi, float* __restrict__ wt1_lo,
                                  float* __restrict__ wt2_hi, float* __restrict__ wt2_lo) {
    int i = blockIdx.x * blockDim.x + threadIdx.x;
    if (i < 256 * F) {
        int n = i >> 7, pos = i & 127;
        int pp = pos & 7;
        int k = (pos & ~7) + (pp >> 1) + ((pp & 1) << 2);   // inverse perm
        float v = (n < 128) ? w1l[k * 128 + n] : w1r[k * 128 + (n - 128)];
        uint2 p = f2tf32p(v);
        wt1_hi[i] = __uint_as_float(p.x);
        wt1_lo[i] = __uint_as_float(p.y);
    } else if (i < 256 * F + 80 * F) {
        int j = i - 256 * F;
        int n = j >> 7, pos = j & 127;
        int pp = pos & 7;
        int k = (pos & ~7) + (pp >> 1) + ((pp & 1) << 2);
        float v = (n < NCLS) ? w2l[k * NCLS + n] : w2r[k * NCLS + (n - NCLS)];
        uint2 p = f2tf32p(v);
        wt2_hi[j] = __uint_as_float(p.x);
        wt2_lo[j] = __uint_as_float(p.y);
    }
}

__global__ void hist_kernel(const void* __restrict__ ei,
                            int* __restrict__ src32, int* __restrict__ dst32,
                            int* __restrict__ cnt, int E) {
    const int mode32 = g_mode32;
    int stride = gridDim.x * blockDim.x;
    for (int e = blockIdx.x * blockDim.x + threadIdx.x; e < E; e += stride) {
        int s, d;
        if (mode32) {
            const int* p = (const int*)ei;
            s = p[e]; d = p[E + e];
        } else {
            const long long* p = (const long long*)ei;
            s = (int)p[e]; d = (int)p[E + e];
        }
        src32[e] = s;
        dst32[e] = d;
        atomicAdd(&cnt[d], 1);
    }
}

__global__ void scan1_kernel(const int* __restrict__ cnt,
                             int* __restrict__ incl, int* __restrict__ bsum) {
    __shared__ int sm[SCB];
    int t = threadIdx.x;
    int i = blockIdx.x * SCB + t;
    int v = (i < NN) ? cnt[i] : 0;
    sm[t] = v;
    __syncthreads();
    for (int off = 1; off < SCB; off <<= 1) {
        int x = (t >= off) ? sm[t - off] : 0;
        __syncthreads();
        sm[t] += x;
        __syncthreads();
    }
    if (i < NN) incl[i] = sm[t];
    if (t == SCB - 1) bsum[blockIdx.x] = sm[t];
}

__global__ void scan2_kernel(const int* __restrict__ bsum, int* __restrict__ bexc) {
    __shared__ int sm[128];
    int t = threadIdx.x;
    int v = (t < NSB) ? bsum[t] : 0;
    sm[t] = v;
    __syncthreads();
    for (int off = 1; off < 128; off <<= 1) {
        int x = (t >= off) ? sm[t - off] : 0;
        __syncthreads();
        sm[t] += x;
        __syncthreads();
    }
    if (t < NSB) bexc[t] = sm[t] - v;
}

__global__ void scan3_kernel(const int* __restrict__ incl,
                             const int* __restrict__ cnt,
                             const int* __restrict__ bexc,
                             int* __restrict__ offs) {
    int i = blockIdx.x * blockDim.x + threadIdx.x;
    if (i < NN) offs[i] = incl[i] - cnt[i] + bexc[i >> 9];
}

__global__ void fill_kernel(const int* __restrict__ src32,
                            const int* __restrict__ dst32,
                            int* __restrict__ offs, int* __restrict__ csr, int E) {
    int stride = gridDim.x * blockDim.x;
    for (int e = blockIdx.x * blockDim.x + threadIdx.x; e < E; e += stride) {
        int d = dst32[e];
        int slot = atomicAdd(&offs[d], 1);
        csr[slot] = src32[e];
    }
}

// ---------------------------------------------------------------------------
// 3xTF32 tensor-core GEMM. A hi/lo split at tile-load (vector stores); B
// pre-split + k-pair-permuted in global -> smem copy, fragments via LDS.64.
// Inner loop: batch-load ALL B frags for a k8, then per-mt A frags + MMAs.
// Epilogue: cols < PHW -> half2 payload (PH, stride PHS); else fp32 to C.
#define MMA_TF32(c, a0, a1, a2, a3, b0, b1)                                 \
    asm volatile(                                                           \
        "mma.sync.aligned.m16n8k8.row.col.f32.tf32.tf32.f32 "               \
        "{%0,%1,%2,%3},{%4,%5,%6,%7},{%8,%9},{%0,%1,%2,%3};"                \
        : "+f"((c)[0]), "+f"((c)[1]), "+f"((c)[2]), "+f"((c)[3])            \
        : "r"(a0), "r"(a1), "r"(a2), "r"(a3), "r"(b0), "r"(b1))

template <int BN, int SWC, int PHW, int PHS>
__global__ __launch_bounds__(256, 2)
void gemm_tc_kernel(const float* __restrict__ A,
                    const float* __restrict__ Bt_hi,   // [BNtot][128] permuted-k
                    const float* __restrict__ Bt_lo,
                    float* __restrict__ C,
                    __half* __restrict__ PH,
                    int Nrows) {
    constexpr int NWT = BN / 16;
    constexpr int KP = 36;
    extern __shared__ float sm[];
    float* As_hi = sm;                     // [128][KP]  (original k order)
    float* As_lo = sm + 128 * KP;
    float* Bs_hi = sm + 2 * 128 * KP;      // [BN][KP]   (permuted k order)
    float* Bs_lo = Bs_hi + BN * KP;
    const uint32_t* uAs_hi = (const uint32_t*)As_hi;
    const uint32_t* uAs_lo = (const uint32_t*)As_lo;
    const uint32_t* uBs_hi = (const uint32_t*)Bs_hi;
    const uint32_t* uBs_lo = (const uint32_t*)Bs_lo;

    int tid = threadIdx.x;
    int lane = tid & 31;
    int warp = tid >> 5;
    int g = lane >> 2, tig = lane & 3;
    int warpRow = warp & 3, warpCol = warp >> 2;
    int brow = blockIdx.x * 128;
    int colbase = blockIdx.y * 128;

    float acc[2][NWT][4];
#pragma unroll
    for (int mt = 0; mt < 2; mt++)
#pragma unroll
        for (int nt = 0; nt < NWT; nt++)
#pragma unroll
            for (int j = 0; j < 4; j++) acc[mt][nt][j] = 0.0f;

#pragma unroll
    for (int ks = 0; ks < 4; ks++) {
        int kc = ks * 32;
        if (ks) __syncthreads();
        // --- A slice (128 x 32): load float4, split, vector-store hi/lo
#pragma unroll
        for (int p = 0; p < 4; p++) {
            int idx = tid + p * 256;
            int m = idx >> 3;
            int kq = (idx & 7) << 2;
            float4 v = make_float4(0.f, 0.f, 0.f, 0.f);
            if (brow + m < Nrows)
                v = *(const float4*)(A + (size_t)(brow + m) * F + kc + kq);
            uint2 px = f2tf32p(v.x), py = f2tf32p(v.y);
            uint2 pz = f2tf32p(v.z), pw = f2tf32p(v.w);
            float4 hv, lv;
            hv.x = __uint_as_float(px.x); lv.x = __uint_as_float(px.y);
            hv.y = __uint_as_float(py.x); lv.y = __uint_as_float(py.y);
            hv.z = __uint_as_float(pz.x); lv.z = __uint_as_float(pz.y);
            hv.w = __uint_as_float(pw.x); lv.w = __uint_as_float(pw.y);
            *(float4*)(As_hi + m * KP + kq) = hv;
            *(float4*)(As_lo + m * KP + kq) = lv;
        }
        // --- B slice (BN x 32): straight copy (already split + permuted)
        constexpr int BF4 = BN * 8;
#pragma unroll
        for (int p = 0; p < (BF4 + 255) / 256; p++) {
            int idx = tid + p * 256;
            if (idx < BF4) {
                int n = idx >> 3;
                int kq = (idx & 7) << 2;
                size_t go = (size_t)(colbase + n) * F + kc + kq;
                *(float4*)(Bs_hi + n * KP + kq) = *(const float4*)(Bt_hi + go);
                *(float4*)(Bs_lo + n * KP + kq) = *(const float4*)(Bt_lo + go);
            }
        }
        __syncthreads();

#pragma unroll
        for (int k8 = 0; k8 < 4; k8++) {
            int kb = k8 * 8;
            // batch-load all B fragments for this k8 (LDS.64 pairs)
            uint32_t bh[NWT][2], bl[NWT][2];
#pragma unroll
            for (int nt = 0; nt < NWT; nt++) {
                int bo = (warpCol * (BN / 2) + nt * 8 + g) * KP + kb + 2 * tig;
                uint2 h2 = *(const uint2*)(uBs_hi + bo);
                uint2 l2 = *(const uint2*)(uBs_lo + bo);
                bh[nt][0] = h2.x; bh[nt][1] = h2.y;
                bl[nt][0] = l2.x; bl[nt][1] = l2.y;
            }
#pragma unroll
            for (int mt = 0; mt < 2; mt++) {
                int ro = (warpRow * 32 + mt * 16 + g) * KP + kb;
                uint32_t ah0 = uAs_hi[ro + tig];
                uint32_t ah1 = uAs_hi[ro + 8 * KP + tig];
                uint32_t ah2 = uAs_hi[ro + tig + 4];
                uint32_t ah3 = uAs_hi[ro + 8 * KP + tig + 4];
                uint32_t al0 = uAs_lo[ro + tig];
                uint32_t al1 = uAs_lo[ro + 8 * KP + tig];
                uint32_t al2 = uAs_lo[ro + tig + 4];
                uint32_t al3 = uAs_lo[ro + 8 * KP + tig + 4];
#pragma unroll
                for (int nt = 0; nt < NWT; nt++) {
                    MMA_TF32(acc[mt][nt], ah0, ah1, ah2, ah3, bh[nt][0], bh[nt][1]);
                    MMA_TF32(acc[mt][nt], ah0, ah1, ah2, ah3, bl[nt][0], bl[nt][1]);
                    MMA_TF32(acc[mt][nt], al0, al1, al2, al3, bh[nt][0], bh[nt][1]);
                }
            }
        }
    }

    // epilogue
#pragma unroll
    for (int mt = 0; mt < 2; mt++) {
#pragma unroll
        for (int nt = 0; nt < NWT; nt++) {
            int row0 = brow + warpRow * 32 + mt * 16 + g;
            int col = colbase + warpCol * (BN / 2) + nt * 8 + 2 * tig;
#pragma unroll
            for (int rr = 0; rr < 2; rr++) {
                int row = row0 + rr * 8;
                if (row >= Nrows) continue;
                float vx = acc[mt][nt][2 * rr + 0];
                float vy = acc[mt][nt][2 * rr + 1];
                if (col < PHW) {
                    __half2 hv = __floats2half2_rn(vx, vy);
                    *(__half2*)(PH + (size_t)row * PHS + col) = hv;
                } else {
                    *(float2*)(C + (size_t)row * SWC + col) = make_float2(vx, vy);
                }
            }
        }
    }
}

// ---------------------------------------------------------------------------
// Layer-1 agg + epilogue: h[n] = relu(mean(p_half[s]) + t[n] + b1)
__global__ void agg1_kernel(const int* __restrict__ csr,
                            const int* __restrict__ offs,
                            const int* __restrict__ cnt,
                            const __half* __restrict__ ph,
                            const float* __restrict__ pt,
                            const float* __restrict__ b1,
                            float* __restrict__ h) {
    int gw = (blockIdx.x * blockDim.x + threadIdx.x) >> 5;
    int lane = threadIdx.x & 31;
    if (gw >= NN) return;
    int dg = cnt[gw];
    int beg = offs[gw] - dg;
    float4 acc0 = make_float4(0.f, 0.f, 0.f, 0.f);
    float4 acc1 = make_float4(0.f, 0.f, 0.f, 0.f);
    int i = 0;
    for (; i + 4 <= dg; i += 4) {
        int s0 = __ldg(&csr[beg + i]);
        int s1 = __ldg(&csr[beg + i + 1]);
        int s2 = __ldg(&csr[beg + i + 2]);
        int s3 = __ldg(&csr[beg + i + 3]);
        uint2 r0 = *(const uint2*)(ph + (size_t)s0 * 128 + lane * 4);
        uint2 r1 = *(const uint2*)(ph + (size_t)s1 * 128 + lane * 4);
        uint2 r2 = *(const uint2*)(ph + (size_t)s2 * 128 + lane * 4);
        uint2 r3 = *(const uint2*)(ph + (size_t)s3 * 128 + lane * 4);
        float2 a0 = __half22float2(*(__half2*)&r0.x), b0 = __half22float2(*(__half2*)&r0.y);
        float2 a1 = __half22float2(*(__half2*)&r1.x), b1v = __half22float2(*(__half2*)&r1.y);
        float2 a2 = __half22float2(*(__half2*)&r2.x), b2v = __half22float2(*(__half2*)&r2.y);
        float2 a3 = __half22float2(*(__half2*)&r3.x), b3v = __half22float2(*(__half2*)&r3.y);
        acc0.x += a0.x + a1.x; acc0.y += a0.y + a1.y;
        acc0.z += b0.x + b1v.x; acc0.w += b0.y + b1v.y;
        acc1.x += a2.x + a3.x; acc1.y += a2.y + a3.y;
        acc1.z += b2v.x + b3v.x; acc1.w += b2v.y + b3v.y;
    }
    for (; i < dg; i++) {
        int s = __ldg(&csr[beg + i]);
        uint2 r0 = *(const uint2*)(ph + (size_t)s * 128 + lane * 4);
        float2 a0 = __half22float2(*(__half2*)&r0.x), b0 = __half22float2(*(__half2*)&r0.y);
        acc0.x += a0.x; acc0.y += a0.y; acc0.z += b0.x; acc0.w += b0.y;
    }
    float inv = 1.0f / fmaxf((float)dg, 1.0f);
    float4 t = *(const float4*)(pt + (size_t)gw * 256 + 128 + lane * 4);
    float4 bb = *(const float4*)(b1 + lane * 4);
    float4 r;
    r.x = fmaxf((acc0.x + acc1.x) * inv + t.x + bb.x, 0.f);
    r.y = fmaxf((acc0.y + acc1.y) * inv + t.y + bb.y, 0.f);
    r.z = fmaxf((acc0.z + acc1.z) * inv + t.z + bb.z, 0.f);
    r.w = fmaxf((acc0.w + acc1.w) * inv + t.w + bb.w, 0.f);
    *(float4*)(h + (size_t)gw * F + lane * 4) = r;
}

// Layer-2: out[n] = mean(q_half[s]) + u[n] + b2.
__global__ void agg2_kernel(const int* __restrict__ csr,
                            const int* __restrict__ offs,
                            const int* __restrict__ cnt,
                            const __half* __restrict__ qh,
                            const float* __restrict__ qu,   // u in cols 40..79, stride 80
                            const float* __restrict__ b2,
                            float* __restrict__ out) {
    int gw = (blockIdx.x * blockDim.x + threadIdx.x) >> 5;
    int lane = threadIdx.x & 31;
    if (gw >= NN) return;
    int dg = cnt[gw];
    int beg = offs[gw] - dg;
    if (lane < 10) {
        float4 acc0 = make_float4(0.f, 0.f, 0.f, 0.f);
        float4 acc1 = make_float4(0.f, 0.f, 0.f, 0.f);
        int i = 0;
        for (; i + 4 <= dg; i += 4) {
            int s0 = __ldg(&csr[beg + i]);
            int s1 = __ldg(&csr[beg + i + 1]);
            int s2 = __ldg(&csr[beg + i + 2]);
            int s3 = __ldg(&csr[beg + i + 3]);
            uint2 r0 = *(const uint2*)(qh + (size_t)s0 * 40 + lane * 4);
            uint2 r1 = *(const uint2*)(qh + (size_t)s1 * 40 + lane * 4);
            uint2 r2 = *(const uint2*)(qh + (size_t)s2 * 40 + lane * 4);
            uint2 r3 = *(const uint2*)(qh + (size_t)s3 * 40 + lane * 4);
            float2 a0 = __half22float2(*(__half2*)&r0.x), b0 = __half22float2(*(__half2*)&r0.y);
            float2 a1 = __half22float2(*(__half2*)&r1.x), b1v = __half22float2(*(__half2*)&r1.y);
            float2 a2 = __half22float2(*(__half2*)&r2.x), b2v = __half22float2(*(__half2*)&r2.y);
            float2 a3 = __half22float2(*(__half2*)&r3.x), b3v = __half22float2(*(__half2*)&r3.y);
            acc0.x += a0.x + a1.x; acc0.y += a0.y + a1.y;
            acc0.z += b0.x + b1v.x; acc0.w += b0.y + b1v.y;
            acc1.x += a2.x + a3.x; acc1.y += a2.y + a3.y;
            acc1.z += b2v.x + b3v.x; acc1.w += b2v.y + b3v.y;
        }
        for (; i < dg; i++) {
            int s = __ldg(&csr[beg + i]);
            uint2 r0 = *(const uint2*)(qh + (size_t)s * 40 + lane * 4);
            float2 a0 = __half22float2(*(__half2*)&r0.x), b0 = __half22float2(*(__half2*)&r0.y);
            acc0.x += a0.x; acc0.y += a0.y; acc0.z += b0.x; acc0.w += b0.y;
        }
        float inv = 1.0f / fmaxf((float)dg, 1.0f);
        float4 uv = *(const float4*)(qu + (size_t)gw * 80 + NCLS + lane * 4);
        float4 bb = *(const float4*)(b2 + lane * 4);
        float4 r;
        r.x = (acc0.x + acc1.x) * inv + uv.x + bb.x;
        r.y = (acc0.y + acc1.y) * inv + uv.y + bb.y;
        r.z = (acc0.z + acc1.z) * inv + uv.z + bb.z;
        r.w = (acc0.w + acc1.w) * inv + uv.w + bb.w;
        *(float4*)(out + (size_t)gw * NCLS + lane * 4) = r;
    }
}

// ---------------------------------------------------------------------------
extern "C" void kernel_launch(void* const* d_in, const int* in_sizes, int n_in,
                              void* d_out, int out_size) {
    const float* x   = (const float*)d_in[0];
    const void*  ei  = d_in[1];
    const float* w1l = (const float*)d_in[2];
    const float* w1r = (const float*)d_in[3];
    const float* b1  = (const float*)d_in[4];
    const float* w2l = (const float*)d_in[5];
    const float* w2r = (const float*)d_in[6];
    const float* b2  = (const float*)d_in[7];
    float* out = (float*)d_out;

    int E = in_sizes[1] / 2;
    int N = in_sizes[0] / F;   // 50000

    float *pPT, *pH, *pW1h, *pW1l, *pW2h, *pW2l;
    __half *pPh, *pQh;
    int *pSrc, *pDst, *pCsr, *pCnt, *pOffs, *pIncl, *pBsum, *pBexc;
    cudaGetSymbolAddress((void**)&pPT,  g_pt);
    cudaGetSymbolAddress((void**)&pH,   g_h);
    cudaGetSymbolAddress((void**)&pPh,  g_ph);
    cudaGetSymbolAddress((void**)&pQh,  g_qh);
    cudaGetSymbolAddress((void**)&pW1h, g_wt1_hi);
    cudaGetSymbolAddress((void**)&pW1l, g_wt1_lo);
    cudaGetSymbolAddress((void**)&pW2h, g_wt2_hi);
    cudaGetSymbolAddress((void**)&pW2l, g_wt2_lo);
    cudaGetSymbolAddress((void**)&pSrc, g_src);
    cudaGetSymbolAddress((void**)&pDst, g_dst);
    cudaGetSymbolAddress((void**)&pCsr, g_csr);
    cudaGetSymbolAddress((void**)&pCnt, g_cnt);
    cudaGetSymbolAddress((void**)&pOffs, g_offs);
    cudaGetSymbolAddress((void**)&pIncl, g_incl);
    cudaGetSymbolAddress((void**)&pBsum, g_bsum);
    cudaGetSymbolAddress((void**)&pBexc, g_bexc);

    const int T = 256;
    int gemm_rows = (N + 127) / 128;          // 391
    int edge_blocks = (E + T - 1) / T;        // 2344
    int warp_blocks = (N * 32 + T - 1) / T;   // 6250

    // dynamic smem opt-in
    const int SMEM1 = (2 * 128 + 2 * 128) * 36 * 4;   // 73728
    const int SMEM2 = (2 * 128 + 2 * 80) * 36 * 4;    // 59904
    cudaFuncSetAttribute(gemm_tc_kernel<128, 256, 128, 128>,
                         cudaFuncAttributeMaxDynamicSharedMemorySize, SMEM1);
    cudaFuncSetAttribute(gemm_tc_kernel<80, 80, 40, 40>,
                         cudaFuncAttributeMaxDynamicSharedMemorySize, SMEM2);

    // Fork-join resources (host-side only; created per call, not destroyed).
    cudaStream_t s2 = 0;
    cudaEvent_t eA = 0, eB = 0;
    bool forked = (cudaStreamCreateWithFlags(&s2, cudaStreamNonBlocking) == cudaSuccess);
    if (forked) forked = (cudaEventCreateWithFlags(&eA, cudaEventDisableTiming) == cudaSuccess);
    if (forked) forked = (cudaEventCreateWithFlags(&eB, cudaEventDisableTiming) == cudaSuccess);
    cudaStream_t sb = forked ? s2 : (cudaStream_t)0;

    // --- main stream: 1 detect, 2 zero, 3 wcat ---
    detect_kernel<<<1, 32>>>(ei);
    zero_int_kernel<<<64, T>>>((int4*)pCnt, NN / 4 + 1);
    build_wcat_kernel<<<(256 * F + 80 * F + T - 1) / T, T>>>(
        w1l, w1r, w2l, w2r, pW1h, pW1l, pW2h, pW2l);

    // fork
    if (forked) {
        cudaEventRecord(eA, 0);
        cudaStreamWaitEvent(s2, eA, 0);
    }

    // 4: layer-1 tensor-core GEMM (profiled launch)
    gemm_tc_kernel<128, 256, 128, 128><<<dim3(gemm_rows, 2), T, SMEM1>>>(
        x, pW1h, pW1l, pPT, pPh, N);

    // CSR chain on branch stream (overlaps gemm1)
    hist_kernel<<<edge_blocks, T, 0, sb>>>(ei, pSrc, pDst, pCnt, E);
    scan1_kernel<<<NSB, SCB, 0, sb>>>(pCnt, pIncl, pBsum);
    scan2_kernel<<<1, 128, 0, sb>>>(pBsum, pBexc);
    scan3_kernel<<<(NN + T - 1) / T, T, 0, sb>>>(pIncl, pCnt, pBexc, pOffs);
    fill_kernel<<<edge_blocks, T, 0, sb>>>(pSrc, pDst, pOffs, pCsr, E);

    // join
    if (forked) {
        cudaEventRecord(eB, s2);
        cudaStreamWaitEvent((cudaStream_t)0, eB, 0);
    }

    // layer-1 aggregation + epilogue -> h
    agg1_kernel<<<warp_blocks, T>>>(pCsr, pOffs, pCnt, pPh, pPT, b1, pH);
    // layer-2 tensor-core GEMM  q(half)/u(fp32) = h @ [w2l|w2r]
    gemm_tc_kernel<80, 80, 40, 40><<<dim3(gemm_rows, 1), T, SMEM2>>>(
        pH, pW2h, pW2l, pPT, pQh, N);
    // layer-2 aggregation + epilogue -> out
    agg2_kernel<<<warp_blocks, T>>>(pCsr, pOffs, pCnt, pQh, pPT, b2, out);
}

// round 14
// speedup vs baseline: 1.0368x; 1.0368x over previous
// R14: R10 GEMM inner loop (conflict-free scalar frags) + R13 half payloads.
#include <cuda_runtime.h>
#include <cuda_fp16.h>
#include <cstdint>

#define NN   50000
#define F    128
#define NCLS 40
#define MAXE 600000
#define SCB  512
#define NSB  ((NN + SCB - 1) / SCB)   // 98

// ---------------- scratch (__device__ globals; no allocations) -------------
__device__ float g_pt[NN * 256];       // layer1: t in cols 128..255 (stride 256); layer2: u in cols 40..79 (stride 80)
__device__ float g_h[NN * F];          // hidden activations
__device__ __half g_ph[NN * 128];      // half payload: p (layer1)
__device__ __half g_qh[NN * 40];       // half payload: q (layer2)
__device__ float g_wt1_hi[256 * F];    // [w1l|w1r]^T hi ([n][k], straight k)
__device__ float g_wt1_lo[256 * F];
__device__ float g_wt2_hi[80 * F];
__device__ float g_wt2_lo[80 * F];
__device__ int g_src[MAXE], g_dst[MAXE], g_csr[MAXE];
__device__ int g_cnt[NN], g_offs[NN], g_incl[NN];
__device__ int g_bsum[NSB], g_bexc[NSB];
__device__ int g_mode32;

// ---------------------------------------------------------------------------
__device__ __forceinline__ uint2 f2tf32p(float a) {
    uint2 r;
    asm("cvt.rna.tf32.f32 %0, %1;" : "=r"(r.x) : "f"(a));
    float t = a - __uint_as_float(r.x);
    asm("cvt.rna.tf32.f32 %0, %1;" : "=r"(r.y) : "f"(t));
    return r;
}

__global__ void detect_kernel(const void* ei) {
    if (threadIdx.x == 0 && blockIdx.x == 0) {
        const long long* p = (const long long*)ei;
        int m32 = 0;
        for (int i = 0; i < 16; i++) {
            long long v = p[i];
            if (v < 0 || v >= NN) { m32 = 1; break; }
        }
        g_mode32 = m32;
    }
}

__global__ void zero_int_kernel(int4* a, int n4) {
    int i = blockIdx.x * blockDim.x + threadIdx.x;
    int stride = gridDim.x * blockDim.x;
    int4 z = make_int4(0, 0, 0, 0);
    for (; i < n4; i += stride) a[i] = z;
}

// Build transposed, tf32-split weight matrices: [n][k] layout (straight k).
__global__ void build_wcat_kernel(const float* __restrict__ w1l,
                                  const float* __restrict__ w1r,
                                  const float* __restrict__ w2l,
                                  const float* __restrict__ w2r,
                                  float* __restrict__ wt1_hi, float* __restrict__ wt1_lo,
                                  float* __restrict__ wt2_hi, float* __restrict__ wt2_lo) {
    int i = blockIdx.x * blockDim.x + threadIdx.x;
    if (i < 256 * F) {
        int n = i >> 7, k = i & 127;
        float v = (n < 128) ? w1l[k * 128 + n] : w1r[k * 128 + (n - 128)];
        uint2 p = f2tf32p(v);
        wt1_hi[i] = __uint_as_float(p.x);
        wt1_lo[i] = __uint_as_float(p.y);
    } else if (i < 256 * F + 80 * F) {
        int j = i - 256 * F;
        int n = j >> 7, k = j & 127;
        float v = (n < NCLS) ? w2l[k * NCLS + n] : w2r[k * NCLS + (n - NCLS)];
        uint2 p = f2tf32p(v);
        wt2_hi[j] = __uint_as_float(p.x);
        wt2_lo[j] = __uint_as_float(p.y);
    }
}

__global__ void hist_kernel(const void* __restrict__ ei,
                            int* __restrict__ src32, int* __restrict__ dst32,
                            int* __restrict__ cnt, int E) {
    const int mode32 = g_mode32;
    int stride = gridDim.x * blockDim.x;
    for (int e = blockIdx.x * blockDim.x + threadIdx.x; e < E; e += stride) {
        int s, d;
        if (mode32) {
            const int* p = (const int*)ei;
            s = p[e]; d = p[E + e];
        } else {
            const long long* p = (const long long*)ei;
            s = (int)p[e]; d = (int)p[E + e];
        }
        src32[e] = s;
        dst32[e] = d;
        atomicAdd(&cnt[d], 1);
    }
}

__global__ void scan1_kernel(const int* __restrict__ cnt,
                             int* __restrict__ incl, int* __restrict__ bsum) {
    __shared__ int sm[SCB];
    int t = threadIdx.x;
    int i = blockIdx.x * SCB + t;
    int v = (i < NN) ? cnt[i] : 0;
    sm[t] = v;
    __syncthreads();
    for (int off = 1; off < SCB; off <<= 1) {
        int x = (t >= off) ? sm[t - off] : 0;
        __syncthreads();
        sm[t] += x;
        __syncthreads();
    }
    if (i < NN) incl[i] = sm[t];
    if (t == SCB - 1) bsum[blockIdx.x] = sm[t];
}

__global__ void scan2_kernel(const int* __restrict__ bsum, int* __restrict__ bexc) {
    __shared__ int sm[128];
    int t = threadIdx.x;
    int v = (t < NSB) ? bsum[t] : 0;
    sm[t] = v;
    __syncthreads();
    for (int off = 1; off < 128; off <<= 1) {
        int x = (t >= off) ? sm[t - off] : 0;
        __syncthreads();
        sm[t] += x;
        __syncthreads();
    }
    if (t < NSB) bexc[t] = sm[t] - v;
}

__global__ void scan3_kernel(const int* __restrict__ incl,
                             const int* __restrict__ cnt,
                             const int* __restrict__ bexc,
                             int* __restrict__ offs) {
    int i = blockIdx.x * blockDim.x + threadIdx.x;
    if (i < NN) offs[i] = incl[i] - cnt[i] + bexc[i >> 9];
}

__global__ void fill_kernel(const int* __restrict__ src32,
                            const int* __restrict__ dst32,
                            int* __restrict__ offs, int* __restrict__ csr, int E) {
    int stride = gridDim.x * blockDim.x;
    for (int e = blockIdx.x * blockDim.x + threadIdx.x; e < E; e += stride) {
        int d = dst32[e];
        int slot = atomicAdd(&offs[d], 1);
        csr[slot] = src32[e];
    }
}

// ---------------------------------------------------------------------------
// 3xTF32 tensor-core GEMM (R10 inner loop: conflict-free scalar fragment
// loads at banks 4g+tig). A hi/lo split at tile-load (vector stores); B
// pre-split in global ([n][k]) -> straight smem copy. KP=36.
// Epilogue: cols < PHW -> half2 payload (PH, stride PHS); else fp32 to C.
#define MMA_TF32(c, a0, a1, a2, a3, b0, b1)                                 \
    asm volatile(                                                           \
        "mma.sync.aligned.m16n8k8.row.col.f32.tf32.tf32.f32 "               \
        "{%0,%1,%2,%3},{%4,%5,%6,%7},{%8,%9},{%0,%1,%2,%3};"                \
        : "+f"((c)[0]), "+f"((c)[1]), "+f"((c)[2]), "+f"((c)[3])            \
        : "r"(a0), "r"(a1), "r"(a2), "r"(a3), "r"(b0), "r"(b1))

template <int BN, int SWC, int PHW, int PHS>
__global__ __launch_bounds__(256, 2)
void gemm_tc_kernel(const float* __restrict__ A,
                    const float* __restrict__ Bt_hi,   // [BNtot][128]
                    const float* __restrict__ Bt_lo,
                    float* __restrict__ C,
                    __half* __restrict__ PH,
                    int Nrows) {
    constexpr int NWT = BN / 16;
    constexpr int KP = 36;
    extern __shared__ float sm[];
    float* As_hi = sm;                     // [128][KP]
    float* As_lo = sm + 128 * KP;
    float* Bs_hi = sm + 2 * 128 * KP;      // [BN][KP]
    float* Bs_lo = Bs_hi + BN * KP;
    const uint32_t* uAs_hi = (const uint32_t*)As_hi;
    const uint32_t* uAs_lo = (const uint32_t*)As_lo;
    const uint32_t* uBs_hi = (const uint32_t*)Bs_hi;
    const uint32_t* uBs_lo = (const uint32_t*)Bs_lo;

    int tid = threadIdx.x;
    int lane = tid & 31;
    int warp = tid >> 5;
    int g = lane >> 2, tig = lane & 3;
    int warpRow = warp & 3, warpCol = warp >> 2;
    int brow = blockIdx.x * 128;
    int colbase = blockIdx.y * 128;

    float acc[2][NWT][4];
#pragma unroll
    for (int mt = 0; mt < 2; mt++)
#pragma unroll
        for (int nt = 0; nt < NWT; nt++)
#pragma unroll
            for (int j = 0; j < 4; j++) acc[mt][nt][j] = 0.0f;

#pragma unroll
    for (int ks = 0; ks < 4; ks++) {
        int kc = ks * 32;
        if (ks) __syncthreads();
        // --- A slice (128 x 32): load float4, split, vector-store hi/lo
#pragma unroll
        for (int p = 0; p < 4; p++) {
            int idx = tid + p * 256;
            int m = idx >> 3;
            int kq = (idx & 7) << 2;
            float4 v = make_float4(0.f, 0.f, 0.f, 0.f);
            if (brow + m < Nrows)
                v = *(const float4*)(A + (size_t)(brow + m) * F + kc + kq);
            uint2 px = f2tf32p(v.x), py = f2tf32p(v.y);
            uint2 pz = f2tf32p(v.z), pw = f2tf32p(v.w);
            float4 hv, lv;
            hv.x = __uint_as_float(px.x); lv.x = __uint_as_float(px.y);
            hv.y = __uint_as_float(py.x); lv.y = __uint_as_float(py.y);
            hv.z = __uint_as_float(pz.x); lv.z = __uint_as_float(pz.y);
            hv.w = __uint_as_float(pw.x); lv.w = __uint_as_float(pw.y);
            *(float4*)(As_hi + m * KP + kq) = hv;
            *(float4*)(As_lo + m * KP + kq) = lv;
        }
        // --- B slice (BN x 32): straight copy from pre-split global
        constexpr int BF4 = BN * 8;
#pragma unroll
        for (int p = 0; p < (BF4 + 255) / 256; p++) {
            int idx = tid + p * 256;
            if (idx < BF4) {
                int n = idx >> 3;
                int kq = (idx & 7) << 2;
                size_t go = (size_t)(colbase + n) * F + kc + kq;
                *(float4*)(Bs_hi + n * KP + kq) = *(const float4*)(Bt_hi + go);
                *(float4*)(Bs_lo + n * KP + kq) = *(const float4*)(Bt_lo + go);
            }
        }
        __syncthreads();

#pragma unroll
        for (int k8 = 0; k8 < 4; k8++) {
            int kb = k8 * 8;
            uint32_t ah[2][4], al[2][4];
#pragma unroll
            for (int mt = 0; mt < 2; mt++) {
                int ro = (warpRow * 32 + mt * 16 + g) * KP + kb;
                ah[mt][0] = uAs_hi[ro + tig];
                ah[mt][1] = uAs_hi[ro + 8 * KP + tig];
                ah[mt][2] = uAs_hi[ro + tig + 4];
                ah[mt][3] = uAs_hi[ro + 8 * KP + tig + 4];
                al[mt][0] = uAs_lo[ro + tig];
                al[mt][1] = uAs_lo[ro + 8 * KP + tig];
                al[mt][2] = uAs_lo[ro + tig + 4];
                al[mt][3] = uAs_lo[ro + 8 * KP + tig + 4];
            }
#pragma unroll
            for (int nt = 0; nt < NWT; nt++) {
                int bo = (warpCol * (BN / 2) + nt * 8 + g) * KP + kb;
                uint32_t bh0 = uBs_hi[bo + tig];
                uint32_t bh1 = uBs_hi[bo + tig + 4];
                uint32_t bl0 = uBs_lo[bo + tig];
                uint32_t bl1 = uBs_lo[bo + tig + 4];
#pragma unroll
                for (int mt = 0; mt < 2; mt++) {
                    MMA_TF32(acc[mt][nt], ah[mt][0], ah[mt][1], ah[mt][2], ah[mt][3], bh0, bh1);
                    MMA_TF32(acc[mt][nt], ah[mt][0], ah[mt][1], ah[mt][2], ah[mt][3], bl0, bl1);
                    MMA_TF32(acc[mt][nt], al[mt][0], al[mt][1], al[mt][2], al[mt][3], bh0, bh1);
                }
            }
        }
    }

    // epilogue
#pragma unroll
    for (int mt = 0; mt < 2; mt++) {
#pragma unroll
        for (int nt = 0; nt < NWT; nt++) {
            int row0 = brow + warpRow * 32 + mt * 16 + g;
            int col = colbase + warpCol * (BN / 2) + nt * 8 + 2 * tig;
#pragma unroll
            for (int rr = 0; rr < 2; rr++) {
                int row = row0 + rr * 8;
                if (row >= Nrows) continue;
                float vx = acc[mt][nt][2 * rr + 0];
                float vy = acc[mt][nt][2 * rr + 1];
                if (col < PHW) {
                    __half2 hv = __floats2half2_rn(vx, vy);
                    *(__half2*)(PH + (size_t)row * PHS + col) = hv;
                } else {
                    *(float2*)(C + (size_t)row * SWC + col) = make_float2(vx, vy);
                }
            }
        }
    }
}

// ---------------------------------------------------------------------------
// Layer-1 agg + epilogue: h[n] = relu(mean(p_half[s]) + t[n] + b1)
__global__ void agg1_kernel(const int* __restrict__ csr,
                            const int* __restrict__ offs,
                            const int* __restrict__ cnt,
                            const __half* __restrict__ ph,
                            const float* __restrict__ pt,
                            const float* __restrict__ b1,
                            float* __restrict__ h) {
    int gw = (blockIdx.x * blockDim.x + threadIdx.x) >> 5;
    int lane = threadIdx.x & 31;
    if (gw >= NN) return;
    int dg = cnt[gw];
    int beg = offs[gw] - dg;
    float4 acc0 = make_float4(0.f, 0.f, 0.f, 0.f);
    float4 acc1 = make_float4(0.f, 0.f, 0.f, 0.f);
    int i = 0;
    for (; i + 4 <= dg; i += 4) {
        int s0 = __ldg(&csr[beg + i]);
        int s1 = __ldg(&csr[beg + i + 1]);
        int s2 = __ldg(&csr[beg + i + 2]);
        int s3 = __ldg(&csr[beg + i + 3]);
        uint2 r0 = *(const uint2*)(ph + (size_t)s0 * 128 + lane * 4);
        uint2 r1 = *(const uint2*)(ph + (size_t)s1 * 128 + lane * 4);
        uint2 r2 = *(const uint2*)(ph + (size_t)s2 * 128 + lane * 4);
        uint2 r3 = *(const uint2*)(ph + (size_t)s3 * 128 + lane * 4);
        float2 a0 = __half22float2(*(__half2*)&r0.x), b0 = __half22float2(*(__half2*)&r0.y);
        float2 a1 = __half22float2(*(__half2*)&r1.x), b1v = __half22float2(*(__half2*)&r1.y);
        float2 a2 = __half22float2(*(__half2*)&r2.x), b2v = __half22float2(*(__half2*)&r2.y);
        float2 a3 = __half22float2(*(__half2*)&r3.x), b3v = __half22float2(*(__half2*)&r3.y);
        acc0.x += a0.x + a1.x; acc0.y += a0.y + a1.y;
        acc0.z += b0.x + b1v.x; acc0.w += b0.y + b1v.y;
        acc1.x += a2.x + a3.x; acc1.y += a2.y + a3.y;
        acc1.z += b2v.x + b3v.x; acc1.w += b2v.y + b3v.y;
    }
    for (; i < dg; i++) {
        int s = __ldg(&csr[beg + i]);
        uint2 r0 = *(const uint2*)(ph + (size_t)s * 128 + lane * 4);
        float2 a0 = __half22float2(*(__half2*)&r0.x), b0 = __half22float2(*(__half2*)&r0.y);
        acc0.x += a0.x; acc0.y += a0.y; acc0.z += b0.x; acc0.w += b0.y;
    }
    float inv = 1.0f / fmaxf((float)dg, 1.0f);
    float4 t = *(const float4*)(pt + (size_t)gw * 256 + 128 + lane * 4);
    float4 bb = *(const float4*)(b1 + lane * 4);
    float4 r;
    r.x = fmaxf((acc0.x + acc1.x) * inv + t.x + bb.x, 0.f);
    r.y = fmaxf((acc0.y + acc1.y) * inv + t.y + bb.y, 0.f);
    r.z = fmaxf((acc0.z + acc1.z) * inv + t.z + bb.z, 0.f);
    r.w = fmaxf((acc0.w + acc1.w) * inv + t.w + bb.w, 0.f);
    *(float4*)(h + (size_t)gw * F + lane * 4) = r;
}

// Layer-2: out[n] = mean(q_half[s]) + u[n] + b2.
__global__ void agg2_kernel(const int* __restrict__ csr,
                            const int* __restrict__ offs,
                            const int* __restrict__ cnt,
                            const __half* __restrict__ qh,
                            const float* __restrict__ qu,   // u in cols 40..79, stride 80
                            const float* __restrict__ b2,
                            float* __restrict__ out) {
    int gw = (blockIdx.x * blockDim.x + threadIdx.x) >> 5;
    int lane = threadIdx.x & 31;
    if (gw >= NN) return;
    int dg = cnt[gw];
    int beg = offs[gw] - dg;
    if (lane < 10) {
        float4 acc0 = make_float4(0.f, 0.f, 0.f, 0.f);
        float4 acc1 = make_float4(0.f, 0.f, 0.f, 0.f);
        int i = 0;
        for (; i + 4 <= dg; i += 4) {
            int s0 = __ldg(&csr[beg + i]);
            int s1 = __ldg(&csr[beg + i + 1]);
            int s2 = __ldg(&csr[beg + i + 2]);
            int s3 = __ldg(&csr[beg + i + 3]);
            uint2 r0 = *(const uint2*)(qh + (size_t)s0 * 40 + lane * 4);
            uint2 r1 = *(const uint2*)(qh + (size_t)s1 * 40 + lane * 4);
            uint2 r2 = *(const uint2*)(qh + (size_t)s2 * 40 + lane * 4);
            uint2 r3 = *(const uint2*)(qh + (size_t)s3 * 40 + lane * 4);
            float2 a0 = __half22float2(*(__half2*)&r0.x), b0 = __half22float2(*(__half2*)&r0.y);
            float2 a1 = __half22float2(*(__half2*)&r1.x), b1v = __half22float2(*(__half2*)&r1.y);
            float2 a2 = __half22float2(*(__half2*)&r2.x), b2v = __half22float2(*(__half2*)&r2.y);
            float2 a3 = __half22float2(*(__half2*)&r3.x), b3v = __half22float2(*(__half2*)&r3.y);
            acc0.x += a0.x + a1.x; acc0.y += a0.y + a1.y;
            acc0.z += b0.x + b1v.x; acc0.w += b0.y + b1v.y;
            acc1.x += a2.x + a3.x; acc1.y += a2.y + a3.y;
            acc1.z += b2v.x + b3v.x; acc1.w += b2v.y + b3v.y;
        }
        for (; i < dg; i++) {
            int s = __ldg(&csr[beg + i]);
            uint2 r0 = *(const uint2*)(qh + (size_t)s * 40 + lane * 4);
            float2 a0 = __half22float2(*(__half2*)&r0.x), b0 = __half22float2(*(__half2*)&r0.y);
            acc0.x += a0.x; acc0.y += a0.y; acc0.z += b0.x; acc0.w += b0.y;
        }
        float inv = 1.0f / fmaxf((float)dg, 1.0f);
        float4 uv = *(const float4*)(qu + (size_t)gw * 80 + NCLS + lane * 4);
        float4 bb = *(const float4*)(b2 + lane * 4);
        float4 r;
        r.x = (acc0.x + acc1.x) * inv + uv.x + bb.x;
        r.y = (acc0.y + acc1.y) * inv + uv.y + bb.y;
        r.z = (acc0.z + acc1.z) * inv + uv.z + bb.z;
        r.w = (acc0.w + acc1.w) * inv + uv.w + bb.w;
        *(float4*)(out + (size_t)gw * NCLS + lane * 4) = r;
    }
}

// ---------------------------------------------------------------------------
extern "C" void kernel_launch(void* const* d_in, const int* in_sizes, int n_in,
                              void* d_out, int out_size) {
    const float* x   = (const float*)d_in[0];
    const void*  ei  = d_in[1];
    const float* w1l = (const float*)d_in[2];
    const float* w1r = (const float*)d_in[3];
    const float* b1  = (const float*)d_in[4];
    const float* w2l = (const float*)d_in[5];
    const float* w2r = (const float*)d_in[6];
    const float* b2  = (const float*)d_in[7];
    float* out = (float*)d_out;

    int E = in_sizes[1] / 2;
    int N = in_sizes[0] / F;   // 50000

    float *pPT, *pH, *pW1h, *pW1l, *pW2h, *pW2l;
    __half *pPh, *pQh;
    int *pSrc, *pDst, *pCsr, *pCnt, *pOffs, *pIncl, *pBsum, *pBexc;
    cudaGetSymbolAddress((void**)&pPT,  g_pt);
    cudaGetSymbolAddress((void**)&pH,   g_h);
    cudaGetSymbolAddress((void**)&pPh,  g_ph);
    cudaGetSymbolAddress((void**)&pQh,  g_qh);
    cudaGetSymbolAddress((void**)&pW1h, g_wt1_hi);
    cudaGetSymbolAddress((void**)&pW1l, g_wt1_lo);
    cudaGetSymbolAddress((void**)&pW2h, g_wt2_hi);
    cudaGetSymbolAddress((void**)&pW2l, g_wt2_lo);
    cudaGetSymbolAddress((void**)&pSrc, g_src);
    cudaGetSymbolAddress((void**)&pDst, g_dst);
    cudaGetSymbolAddress((void**)&pCsr, g_csr);
    cudaGetSymbolAddress((void**)&pCnt, g_cnt);
    cudaGetSymbolAddress((void**)&pOffs, g_offs);
    cudaGetSymbolAddress((void**)&pIncl, g_incl);
    cudaGetSymbolAddress((void**)&pBsum, g_bsum);
    cudaGetSymbolAddress((void**)&pBexc, g_bexc);

    const int T = 256;
    int gemm_rows = (N + 127) / 128;          // 391
    int edge_blocks = (E + T - 1) / T;        // 2344
    int warp_blocks = (N * 32 + T - 1) / T;   // 6250

    // dynamic smem opt-in
    const int SMEM1 = (2 * 128 + 2 * 128) * 36 * 4;   // 73728
    const int SMEM2 = (2 * 128 + 2 * 80) * 36 * 4;    // 59904
    cudaFuncSetAttribute(gemm_tc_kernel<128, 256, 128, 128>,
                         cudaFuncAttributeMaxDynamicSharedMemorySize, SMEM1);
    cudaFuncSetAttribute(gemm_tc_kernel<80, 80, 40, 40>,
                         cudaFuncAttributeMaxDynamicSharedMemorySize, SMEM2);

    // Fork-join resources (host-side only; created per call, not destroyed).
    cudaStream_t s2 = 0;
    cudaEvent_t eA = 0, eB = 0;
    bool forked = (cudaStreamCreateWithFlags(&s2, cudaStreamNonBlocking) == cudaSuccess);
    if (forked) forked = (cudaEventCreateWithFlags(&eA, cudaEventDisableTiming) == cudaSuccess);
    if (forked) forked = (cudaEventCreateWithFlags(&eB, cudaEventDisableTiming) == cudaSuccess);
    cudaStream_t sb = forked ? s2 : (cudaStream_t)0;

    // --- main stream: 1 detect, 2 zero, 3 wcat ---
    detect_kernel<<<1, 32>>>(ei);
    zero_int_kernel<<<64, T>>>((int4*)pCnt, NN / 4 + 1);
    build_wcat_kernel<<<(256 * F + 80 * F + T - 1) / T, T>>>(
        w1l, w1r, w2l, w2r, pW1h, pW1l, pW2h, pW2l);

    // fork
    if (forked) {
        cudaEventRecord(eA, 0);
        cudaStreamWaitEvent(s2, eA, 0);
    }

    // 4: layer-1 tensor-core GEMM (profiled launch)
    gemm_tc_kernel<128, 256, 128, 128><<<dim3(gemm_rows, 2), T, SMEM1>>>(
        x, pW1h, pW1l, pPT, pPh, N);

    // CSR chain on branch stream (overlaps gemm1)
    hist_kernel<<<edge_blocks, T, 0, sb>>>(ei, pSrc, pDst, pCnt, E);
    scan1_kernel<<<NSB, SCB, 0, sb>>>(pCnt, pIncl, pBsum);
    scan2_kernel<<<1, 128, 0, sb>>>(pBsum, pBexc);
    scan3_kernel<<<(NN + T - 1) / T, T, 0, sb>>>(pIncl, pCnt, pBexc, pOffs);
    fill_kernel<<<edge_blocks, T, 0, sb>>>(pSrc, pDst, pOffs, pCsr, E);

    // join
    if (forked) {
        cudaEventRecord(eB, s2);
        cudaStreamWaitEvent((cudaStream_t)0, eB, 0);
    }

    // layer-1 aggregation + epilogue -> h
    agg1_kernel<<<warp_blocks, T>>>(pCsr, pOffs, pCnt, pPh, pPT, b1, pH);
    // layer-2 tensor-core GEMM  q(half)/u(fp32) = h @ [w2l|w2r]
    gemm_tc_kernel<80, 80, 40, 40><<<dim3(gemm_rows, 1), T, SMEM2>>>(
        pH, pW2h, pW2l, pPT, pQh, N);
    // layer-2 aggregation + epilogue -> out
    agg2_kernel<<<warp_blocks, T>>>(pCsr, pOffs, pCnt, pQh, pPT, b2, out);
}

// round 17
// speedup vs baseline: 1.0520x; 1.0146x over previous
// R17: third submission of the R15 kernel (R15+R16 died on broker infra
// pre-execution; R13 precedent shows identical code passing on 3rd try).
// = R10 base (best passing, 162.3us) + B-fragment rotation in gemm inner loop.
#include <cuda_runtime.h>
#include <cstdint>

#define NN   50000
#define F    128
#define NCLS 40
#define MAXE 600000
#define SCB  512
#define NSB  ((NN + SCB - 1) / SCB)   // 98

// ---------------- scratch (__device__ globals; no allocations) -------------
__device__ float g_pt[NN * 256];       // layer1: [p|t] (stride 256); layer2: [q|u] (stride 80)
__device__ float g_h[NN * F];          // hidden activations
__device__ float g_wt1_hi[256 * F];    // [w1l|w1r]^T hi  (n-major: [n][k])
__device__ float g_wt1_lo[256 * F];
__device__ float g_wt2_hi[80 * F];     // [w2l|w2r]^T hi
__device__ float g_wt2_lo[80 * F];
__device__ int g_src[MAXE], g_dst[MAXE], g_csr[MAXE];
__device__ int g_cnt[NN], g_offs[NN], g_incl[NN];
__device__ int g_bsum[NSB], g_bexc[NSB];
__device__ int g_mode32;

// ---------------------------------------------------------------------------
__device__ __forceinline__ uint2 f2tf32p(float a) {
    uint2 r;
    asm("cvt.rna.tf32.f32 %0, %1;" : "=r"(r.x) : "f"(a));
    float t = a - __uint_as_float(r.x);
    asm("cvt.rna.tf32.f32 %0, %1;" : "=r"(r.y) : "f"(t));
    return r;
}

__global__ void detect_kernel(const void* ei) {
    if (threadIdx.x == 0 && blockIdx.x == 0) {
        const long long* p = (const long long*)ei;
        int m32 = 0;
        for (int i = 0; i < 16; i++) {
            long long v = p[i];
            if (v < 0 || v >= NN) { m32 = 1; break; }
        }
        g_mode32 = m32;
    }
}

__global__ void zero_int_kernel(int4* a, int n4) {
    int i = blockIdx.x * blockDim.x + threadIdx.x;
    int stride = gridDim.x * blockDim.x;
    int4 z = make_int4(0, 0, 0, 0);
    for (; i < n4; i += stride) a[i] = z;
}

// Build transposed, tf32-split weight matrices: [n][k] layout.
__global__ void build_wcat_kernel(const float* __restrict__ w1l,
                                  const float* __restrict__ w1r,
                                  const float* __restrict__ w2l,
                                  const float* __restrict__ w2r,
                                  float* __restrict__ wt1_hi, float* __restrict__ wt1_lo,
                                  float* __restrict__ wt2_hi, float* __restrict__ wt2_lo) {
    int i = blockIdx.x * blockDim.x + threadIdx.x;
    if (i < 256 * F) {
        int n = i >> 7, k = i & 127;
        float v = (n < 128) ? w1l[k * 128 + n] : w1r[k * 128 + (n - 128)];
        uint2 p = f2tf32p(v);
        wt1_hi[i] = __uint_as_float(p.x);
        wt1_lo[i] = __uint_as_float(p.y);
    } else if (i < 256 * F + 80 * F) {
        int j = i - 256 * F;
        int n = j >> 7, k = j & 127;
        float v = (n < NCLS) ? w2l[k * NCLS + n] : w2r[k * NCLS + (n - NCLS)];
        uint2 p = f2tf32p(v);
        wt2_hi[j] = __uint_as_float(p.x);
        wt2_lo[j] = __uint_as_float(p.y);
    }
}

__global__ void hist_kernel(const void* __restrict__ ei,
                            int* __restrict__ src32, int* __restrict__ dst32,
                            int* __restrict__ cnt, int E) {
    const int mode32 = g_mode32;
    int stride = gridDim.x * blockDim.x;
    for (int e = blockIdx.x * blockDim.x + threadIdx.x; e < E; e += stride) {
        int s, d;
        if (mode32) {
            const int* p = (const int*)ei;
            s = p[e]; d = p[E + e];
        } else {
            const long long* p = (const long long*)ei;
            s = (int)p[e]; d = (int)p[E + e];
        }
        src32[e] = s;
        dst32[e] = d;
        atomicAdd(&cnt[d], 1);
    }
}

__global__ void scan1_kernel(const int* __restrict__ cnt,
                             int* __restrict__ incl, int* __restrict__ bsum) {
    __shared__ int sm[SCB];
    int t = threadIdx.x;
    int i = blockIdx.x * SCB + t;
    int v = (i < NN) ? cnt[i] : 0;
    sm[t] = v;
    __syncthreads();
    for (int off = 1; off < SCB; off <<= 1) {
        int x = (t >= off) ? sm[t - off] : 0;
        __syncthreads();
        sm[t] += x;
        __syncthreads();
    }
    if (i < NN) incl[i] = sm[t];
    if (t == SCB - 1) bsum[blockIdx.x] = sm[t];
}

__global__ void scan2_kernel(const int* __restrict__ bsum, int* __restrict__ bexc) {
    __shared__ int sm[128];
    int t = threadIdx.x;
    int v = (t < NSB) ? bsum[t] : 0;
    sm[t] = v;
    __syncthreads();
    for (int off = 1; off < 128; off <<= 1) {
        int x = (t >= off) ? sm[t - off] : 0;
        __syncthreads();
        sm[t] += x;
        __syncthreads();
    }
    if (t < NSB) bexc[t] = sm[t] - v;
}

__global__ void scan3_kernel(const int* __restrict__ incl,
                             const int* __restrict__ cnt,
                             const int* __restrict__ bexc,
                             int* __restrict__ offs) {
    int i = blockIdx.x * blockDim.x + threadIdx.x;
    if (i < NN) offs[i] = incl[i] - cnt[i] + bexc[i >> 9];
}

__global__ void fill_kernel(const int* __restrict__ src32,
                            const int* __restrict__ dst32,
                            int* __restrict__ offs, int* __restrict__ csr, int E) {
    int stride = gridDim.x * blockDim.x;
    for (int e = blockIdx.x * blockDim.x + threadIdx.x; e < E; e += stride) {
        int d = dst32[e];
        int slot = atomicAdd(&offs[d], 1);
        csr[slot] = src32[e];
    }
}

// ---------------------------------------------------------------------------
// 3xTF32 tensor-core GEMM. Conflict-free scalar fragment loads (banks 4g+tig)
// with the B fragments software-rotated one nt ahead to hide LDS latency.
// A hi/lo split at tile-load (vector stores); B pre-split in global ([n][k]).
#define MMA_TF32(c, a0, a1, a2, a3, b0, b1)                                 \
    asm volatile(                                                           \
        "mma.sync.aligned.m16n8k8.row.col.f32.tf32.tf32.f32 "               \
        "{%0,%1,%2,%3},{%4,%5,%6,%7},{%8,%9},{%0,%1,%2,%3};"                \
        : "+f"((c)[0]), "+f"((c)[1]), "+f"((c)[2]), "+f"((c)[3])            \
        : "r"(a0), "r"(a1), "r"(a2), "r"(a3), "r"(b0), "r"(b1))

template <int BN, int SWC>
__global__ __launch_bounds__(256, 2)
void gemm_tc_kernel(const float* __restrict__ A,
                    const float* __restrict__ Bt_hi,   // [BNtot][128]
                    const float* __restrict__ Bt_lo,
                    float* __restrict__ C,
                    int Nrows) {
    constexpr int NWT = BN / 16;
    constexpr int KP = 36;
    extern __shared__ float sm[];
    float* As_hi = sm;                     // [128][KP]
    float* As_lo = sm + 128 * KP;
    float* Bs_hi = sm + 2 * 128 * KP;      // [BN][KP]
    float* Bs_lo = Bs_hi + BN * KP;
    const uint32_t* uAs_hi = (const uint32_t*)As_hi;
    const uint32_t* uAs_lo = (const uint32_t*)As_lo;
    const uint32_t* uBs_hi = (const uint32_t*)Bs_hi;
    const uint32_t* uBs_lo = (const uint32_t*)Bs_lo;

    int tid = threadIdx.x;
    int lane = tid & 31;
    int warp = tid >> 5;
    int g = lane >> 2, tig = lane & 3;
    int warpRow = warp & 3, warpCol = warp >> 2;
    int brow = blockIdx.x * 128;
    int colbase = blockIdx.y * 128;

    float acc[2][NWT][4];
#pragma unroll
    for (int mt = 0; mt < 2; mt++)
#pragma unroll
        for (int nt = 0; nt < NWT; nt++)
#pragma unroll
            for (int j = 0; j < 4; j++) acc[mt][nt][j] = 0.0f;

#pragma unroll
    for (int ks = 0; ks < 4; ks++) {
        int kc = ks * 32;
        if (ks) __syncthreads();
        // --- A slice (128 x 32): load float4, split, vector-store hi/lo
#pragma unroll
        for (int p = 0; p < 4; p++) {
            int idx = tid + p * 256;
            int m = idx >> 3;
            int kq = (idx & 7) << 2;
            float4 v = make_float4(0.f, 0.f, 0.f, 0.f);
            if (brow + m < Nrows)
                v = *(const float4*)(A + (size_t)(brow + m) * F + kc + kq);
            uint2 px = f2tf32p(v.x), py = f2tf32p(v.y);
            uint2 pz = f2tf32p(v.z), pw = f2tf32p(v.w);
            float4 hv, lv;
            hv.x = __uint_as_float(px.x); lv.x = __uint_as_float(px.y);
            hv.y = __uint_as_float(py.x); lv.y = __uint_as_float(py.y);
            hv.z = __uint_as_float(pz.x); lv.z = __uint_as_float(pz.y);
            hv.w = __uint_as_float(pw.x); lv.w = __uint_as_float(pw.y);
            *(float4*)(As_hi + m * KP + kq) = hv;
            *(float4*)(As_lo + m * KP + kq) = lv;
        }
        // --- B slice (BN x 32): straight copy from pre-split global
        constexpr int BF4 = BN * 8;
#pragma unroll
        for (int p = 0; p < (BF4 + 255) / 256; p++) {
            int idx = tid + p * 256;
            if (idx < BF4) {
                int n = idx >> 3;
                int kq = (idx & 7) << 2;
                size_t go = (size_t)(colbase + n) * F + kc + kq;
                *(float4*)(Bs_hi + n * KP + kq) = *(const float4*)(Bt_hi + go);
                *(float4*)(Bs_lo + n * KP + kq) = *(const float4*)(Bt_lo + go);
            }
        }
        __syncthreads();

#pragma unroll
        for (int k8 = 0; k8 < 4; k8++) {
            int kb = k8 * 8;
            // A fragments for this k8
            uint32_t ah[2][4], al[2][4];
#pragma unroll
            for (int mt = 0; mt < 2; mt++) {
                int ro = (warpRow * 32 + mt * 16 + g) * KP + kb;
                ah[mt][0] = uAs_hi[ro + tig];
                ah[mt][1] = uAs_hi[ro + 8 * KP + tig];
                ah[mt][2] = uAs_hi[ro + tig + 4];
                ah[mt][3] = uAs_hi[ro + 8 * KP + tig + 4];
                al[mt][0] = uAs_lo[ro + tig];
                al[mt][1] = uAs_lo[ro + 8 * KP + tig];
                al[mt][2] = uAs_lo[ro + tig + 4];
                al[mt][3] = uAs_lo[ro + 8 * KP + tig + 4];
            }
            // B fragments rotated one nt ahead
            int bo0 = (warpCol * (BN / 2) + g) * KP + kb;
            uint32_t bh0 = uBs_hi[bo0 + tig];
            uint32_t bh1 = uBs_hi[bo0 + tig + 4];
            uint32_t bl0 = uBs_lo[bo0 + tig];
            uint32_t bl1 = uBs_lo[bo0 + tig + 4];
#pragma unroll
            for (int nt = 0; nt < NWT; nt++) {
                uint32_t nbh0, nbh1, nbl0, nbl1;
                if (nt + 1 < NWT) {
                    int bo = (warpCol * (BN / 2) + (nt + 1) * 8 + g) * KP + kb;
                    nbh0 = uBs_hi[bo + tig];
                    nbh1 = uBs_hi[bo + tig + 4];
                    nbl0 = uBs_lo[bo + tig];
                    nbl1 = uBs_lo[bo + tig + 4];
                }
#pragma unroll
                for (int mt = 0; mt < 2; mt++) {
                    MMA_TF32(acc[mt][nt], ah[mt][0], ah[mt][1], ah[mt][2], ah[mt][3], bh0, bh1);
                    MMA_TF32(acc[mt][nt], ah[mt][0], ah[mt][1], ah[mt][2], ah[mt][3], bl0, bl1);
                    MMA_TF32(acc[mt][nt], al[mt][0], al[mt][1], al[mt][2], al[mt][3], bh0, bh1);
                }
                if (nt + 1 < NWT) {
                    bh0 = nbh0; bh1 = nbh1; bl0 = nbl0; bl1 = nbl1;
                }
            }
        }
    }

    // epilogue: c0,c1 = (row, 2tig..2tig+1), c2,c3 = (row+8, ...)
#pragma unroll
    for (int mt = 0; mt < 2; mt++) {
#pragma unroll
        for (int nt = 0; nt < NWT; nt++) {
            int row0 = brow + warpRow * 32 + mt * 16 + g;
            int col = colbase + warpCol * (BN / 2) + nt * 8 + 2 * tig;
            if (row0 < Nrows) {
                float2 v = make_float2(acc[mt][nt][0], acc[mt][nt][1]);
                *(float2*)(C + (size_t)row0 * SWC + col) = v;
            }
            if (row0 + 8 < Nrows) {
                float2 v = make_float2(acc[mt][nt][2], acc[mt][nt][3]);
                *(float2*)(C + (size_t)(row0 + 8) * SWC + col) = v;
            }
        }
    }
}

// ---------------------------------------------------------------------------
// Layer-1 aggregation + epilogue: h[n] = relu(mean_{s in N(n)} p[s] + t[n] + b1)
__global__ void agg1_kernel(const int* __restrict__ csr,
                            const int* __restrict__ offs,
                            const int* __restrict__ cnt,
                            const float* __restrict__ pt,
                            const float* __restrict__ b1,
                            float* __restrict__ h) {
    int gw = (blockIdx.x * blockDim.x + threadIdx.x) >> 5;
    int lane = threadIdx.x & 31;
    if (gw >= NN) return;
    int dg = cnt[gw];
    int beg = offs[gw] - dg;
    float4 acc0 = make_float4(0.f, 0.f, 0.f, 0.f);
    float4 acc1 = make_float4(0.f, 0.f, 0.f, 0.f);
    int i = 0;
    for (; i + 4 <= dg; i += 4) {
        int s0 = __ldg(&csr[beg + i]);
        int s1 = __ldg(&csr[beg + i + 1]);
        int s2 = __ldg(&csr[beg + i + 2]);
        int s3 = __ldg(&csr[beg + i + 3]);
        float4 v0 = *(const float4*)(pt + (long long)s0 * 256 + lane * 4);
        float4 v1 = *(const float4*)(pt + (long long)s1 * 256 + lane * 4);
        float4 v2 = *(const float4*)(pt + (long long)s2 * 256 + lane * 4);
        float4 v3 = *(const float4*)(pt + (long long)s3 * 256 + lane * 4);
        acc0.x += v0.x + v1.x; acc0.y += v0.y + v1.y;
        acc0.z += v0.z + v1.z; acc0.w += v0.w + v1.w;
        acc1.x += v2.x + v3.x; acc1.y += v2.y + v3.y;
        acc1.z += v2.z + v3.z; acc1.w += v2.w + v3.w;
    }
    for (; i < dg; i++) {
        int s = __ldg(&csr[beg + i]);
        float4 v = *(const float4*)(pt + (long long)s * 256 + lane * 4);
        acc0.x += v.x; acc0.y += v.y; acc0.z += v.z; acc0.w += v.w;
    }
    float inv = 1.0f / fmaxf((float)dg, 1.0f);
    float4 t = *(const float4*)(pt + (long long)gw * 256 + 128 + lane * 4);
    float4 bb = *(const float4*)(b1 + lane * 4);
    float4 r;
    r.x = fmaxf((acc0.x + acc1.x) * inv + t.x + bb.x, 0.f);
    r.y = fmaxf((acc0.y + acc1.y) * inv + t.y + bb.y, 0.f);
    r.z = fmaxf((acc0.z + acc1.z) * inv + t.z + bb.z, 0.f);
    r.w = fmaxf((acc0.w + acc1.w) * inv + t.w + bb.w, 0.f);
    *(float4*)(h + (long long)gw * F + lane * 4) = r;
}

// Layer-2: out[n] = mean q[s] + u[n] + b2. qu stride 80: q=0:40, u=40:80.
__global__ void agg2_kernel(const int* __restrict__ csr,
                            const int* __restrict__ offs,
                            const int* __restrict__ cnt,
                            const float* __restrict__ qu,
                            const float* __restrict__ b2,
                            float* __restrict__ out) {
    int gw = (blockIdx.x * blockDim.x + threadIdx.x) >> 5;
    int lane = threadIdx.x & 31;
    if (gw >= NN) return;
    int dg = cnt[gw];
    int beg = offs[gw] - dg;
    if (lane < 10) {
        float4 acc0 = make_float4(0.f, 0.f, 0.f, 0.f);
        float4 acc1 = make_float4(0.f, 0.f, 0.f, 0.f);
        int i = 0;
        for (; i + 4 <= dg; i += 4) {
            int s0 = __ldg(&csr[beg + i]);
            int s1 = __ldg(&csr[beg + i + 1]);
            int s2 = __ldg(&csr[beg + i + 2]);
            int s3 = __ldg(&csr[beg + i + 3]);
            float4 v0 = *(const float4*)(qu + (long long)s0 * 80 + lane * 4);
            float4 v1 = *(const float4*)(qu + (long long)s1 * 80 + lane * 4);
            float4 v2 = *(const float4*)(qu + (long long)s2 * 80 + lane * 4);
            float4 v3 = *(const float4*)(qu + (long long)s3 * 80 + lane * 4);
            acc0.x += v0.x + v1.x; acc0.y += v0.y + v1.y;
            acc0.z += v0.z + v1.z; acc0.w += v0.w + v1.w;
            acc1.x += v2.x + v3.x; acc1.y += v2.y + v3.y;
            acc1.z += v2.z + v3.z; acc1.w += v2.w + v3.w;
        }
        for (; i < dg; i++) {
            int s = __ldg(&csr[beg + i]);
            float4 v = *(const float4*)(qu + (long long)s * 80 + lane * 4);
            acc0.x += v.x; acc0.y += v.y; acc0.z += v.z; acc0.w += v.w;
        }
        float inv = 1.0f / fmaxf((float)dg, 1.0f);
        float4 uv = *(const float4*)(qu + (long long)gw * 80 + NCLS + lane * 4);
        float4 bb = *(const float4*)(b2 + lane * 4);
        float4 r;
        r.x = (acc0.x + acc1.x) * inv + uv.x + bb.x;
        r.y = (acc0.y + acc1.y) * inv + uv.y + bb.y;
        r.z = (acc0.z + acc1.z) * inv + uv.z + bb.z;
        r.w = (acc0.w + acc1.w) * inv + uv.w + bb.w;
        *(float4*)(out + (long long)gw * NCLS + lane * 4) = r;
    }
}

// ---------------------------------------------------------------------------
extern "C" void kernel_launch(void* const* d_in, const int* in_sizes, int n_in,
                              void* d_out, int out_size) {
    const float* x   = (const float*)d_in[0];
    const void*  ei  = d_in[1];
    const float* w1l = (const float*)d_in[2];
    const float* w1r = (const float*)d_in[3];
    const float* b1  = (const float*)d_in[4];
    const float* w2l = (const float*)d_in[5];
    const float* w2r = (const float*)d_in[6];
    const float* b2  = (const float*)d_in[7];
    float* out = (float*)d_out;

    int E = in_sizes[1] / 2;
    int N = in_sizes[0] / F;   // 50000

    float *pPT, *pH, *pW1h, *pW1l, *pW2h, *pW2l;
    int *pSrc, *pDst, *pCsr, *pCnt, *pOffs, *pIncl, *pBsum, *pBexc;
    cudaGetSymbolAddress((void**)&pPT,  g_pt);
    cudaGetSymbolAddress((void**)&pH,   g_h);
    cudaGetSymbolAddress((void**)&pW1h, g_wt1_hi);
    cudaGetSymbolAddress((void**)&pW1l, g_wt1_lo);
    cudaGetSymbolAddress((void**)&pW2h, g_wt2_hi);
    cudaGetSymbolAddress((void**)&pW2l, g_wt2_lo);
    cudaGetSymbolAddress((void**)&pSrc, g_src);
    cudaGetSymbolAddress((void**)&pDst, g_dst);
    cudaGetSymbolAddress((void**)&pCsr, g_csr);
    cudaGetSymbolAddress((void**)&pCnt, g_cnt);
    cudaGetSymbolAddress((void**)&pOffs, g_offs);
    cudaGetSymbolAddress((void**)&pIncl, g_incl);
    cudaGetSymbolAddress((void**)&pBsum, g_bsum);
    cudaGetSymbolAddress((void**)&pBexc, g_bexc);

    const int T = 256;
    int gemm_rows = (N + 127) / 128;          // 391
    int edge_blocks = (E + T - 1) / T;        // 2344
    int warp_blocks = (N * 32 + T - 1) / T;   // 6250

    // dynamic smem opt-in
    const int SMEM1 = (2 * 128 + 2 * 128) * 36 * 4;   // 73728
    const int SMEM2 = (2 * 128 + 2 * 80) * 36 * 4;    // 59904
    cudaFuncSetAttribute(gemm_tc_kernel<128, 256>,
                         cudaFuncAttributeMaxDynamicSharedMemorySize, SMEM1);
    cudaFuncSetAttribute(gemm_tc_kernel<80, 80>,
                         cudaFuncAttributeMaxDynamicSharedMemorySize, SMEM2);

    // Fork-join resources (host-side only; created per call, not destroyed).
    cudaStream_t s2 = 0;
    cudaEvent_t eA = 0, eB = 0;
    bool forked = (cudaStreamCreateWithFlags(&s2, cudaStreamNonBlocking) == cudaSuccess);
    if (forked) forked = (cudaEventCreateWithFlags(&eA, cudaEventDisableTiming) == cudaSuccess);
    if (forked) forked = (cudaEventCreateWithFlags(&eB, cudaEventDisableTiming) == cudaSuccess);
    cudaStream_t sb = forked ? s2 : (cudaStream_t)0;

    // --- main stream: 1 detect, 2 zero, 3 wcat ---
    detect_kernel<<<1, 32>>>(ei);
    zero_int_kernel<<<64, T>>>((int4*)pCnt, NN / 4 + 1);
    build_wcat_kernel<<<(256 * F + 80 * F + T - 1) / T, T>>>(
        w1l, w1r, w2l, w2r, pW1h, pW1l, pW2h, pW2l);

    // fork
    if (forked) {
        cudaEventRecord(eA, 0);
        cudaStreamWaitEvent(s2, eA, 0);
    }

    // 4: layer-1 tensor-core GEMM (profiled launch)
    gemm_tc_kernel<128, 256><<<dim3(gemm_rows, 2), T, SMEM1>>>(
        x, pW1h, pW1l, pPT, N);

    // CSR chain on branch stream (overlaps gemm1)
    hist_kernel<<<edge_blocks, T, 0, sb>>>(ei, pSrc, pDst, pCnt, E);
    scan1_kernel<<<NSB, SCB, 0, sb>>>(pCnt, pIncl, pBsum);
    scan2_kernel<<<1, 128, 0, sb>>>(pBsum, pBexc);
    scan3_kernel<<<(NN + T - 1) / T, T, 0, sb>>>(pIncl, pCnt, pBexc, pOffs);
    fill_kernel<<<edge_blocks, T, 0, sb>>>(pSrc, pDst, pOffs, pCsr, E);

    // join
    if (forked) {
        cudaEventRecord(eB, s2);
        cudaStreamWaitEvent((cudaStream_t)0, eB, 0);
    }

    // layer-1 aggregation + epilogue -> h
    agg1_kernel<<<warp_blocks, T>>>(pCsr, pOffs, pCnt, pPT, b1, pH);
    // layer-2 tensor-core GEMM  qu = h @ [w2l|w2r]
    gemm_tc_kernel<80, 80><<<dim3(gemm_rows, 1), T, SMEM2>>>(
        pH, pW2h, pW2l, pPT, N);
    // layer-2 aggregation + epilogue -> out
    agg2_kernel<<<warp_blocks, T>>>(pCsr, pOffs, pCnt, pPT, b2, out);
}